// round 16
// baseline (speedup 1.0000x reference)
#include <cuda_runtime.h>
#include <cuda_bf16.h>
#include <cstdint>

// qpNet: z = max(-(x @ W^T + b), -1/EPS), EPS=1e-3  =>  z = max(-h, -1000)
// x: [B,5] f32, W: [5,5] f32, b: [5] f32, out: [B,5] f32. B = 4194304.
//
// R16: warp-independent pipelines with 5120 B per-warp chunks (256 rows),
// ONE TMA load per warp, computed in two 128-row passes; the first half's
// 2560 B store overlaps the second half's compute. 4096 CTAs x 128 thr,
// no block-wide sync anywhere.

#define NEG_CLAMP     (-1000.0f)   // -1/EPS
#define CTA_FLOATS    5120         // 1024 rows
#define WARP_FLOATS   1280         // 256 rows
#define WARP_F4       320
#define HALF_FLOATS   640          // 128 rows
#define HALF_F4       160
#define WARP_BYTES    5120u
#define HALF_BYTES    2560u

__global__ __launch_bounds__(128) void qp_kernel(
    const float* __restrict__ x,
    const float* __restrict__ W,
    const float* __restrict__ b,
    float* __restrict__ out)
{
    __shared__ alignas(128) float4 buf[1280];           // 20 KB, in-place
    __shared__ alignas(8)   unsigned long long mbar[4]; // one per warp

    const int tid  = threadIdx.x;
    const int wid  = tid >> 5;
    const int lane = tid & 31;

    const unsigned mb = (unsigned)__cvta_generic_to_shared(&mbar[wid]);
    const unsigned sb = (unsigned)__cvta_generic_to_shared(buf)
                        + (unsigned)wid * WARP_BYTES;

    const long long base_f = (long long)blockIdx.x * CTA_FLOATS
                           + (long long)wid * WARP_FLOATS;

    uint64_t pol_ld, pol_st;
    asm("createpolicy.fractional.L2::evict_last.b64 %0, 1.0;"  : "=l"(pol_ld));
    asm("createpolicy.fractional.L2::evict_first.b64 %0, 1.0;" : "=l"(pol_st));

    // ---- warp-private: init mbarrier, issue ONE 5120 B bulk load ----
    if (lane == 0) {
        asm volatile("mbarrier.init.shared.b64 [%0], %1;" :: "r"(mb), "r"(1u));
    }
    __syncwarp();
    if (lane == 0) {
        asm volatile("mbarrier.arrive.expect_tx.shared.b64 _, [%0], %1;"
                     :: "r"(mb), "r"(WARP_BYTES) : "memory");
        asm volatile("cp.async.bulk.shared::cta.global.mbarrier::complete_tx::bytes"
                     ".L2::cache_hint [%0], [%1], %2, [%3], %4;"
                     :: "r"(sb),
                        "l"((unsigned long long)(uintptr_t)(x + base_f)),
                        "r"(WARP_BYTES), "r"(mb), "l"(pol_ld) : "memory");
    }

    // ---- W [5,5] + b [5] while TMA is in flight ----
    float w[5][5], bb[5];
    {
        const float4* W4 = reinterpret_cast<const float4*>(W);
        float4 a0 = __ldg(W4 + 0);
        float4 a1 = __ldg(W4 + 1);
        float4 a2 = __ldg(W4 + 2);
        float4 a3 = __ldg(W4 + 3);
        float4 a4 = __ldg(W4 + 4);
        float4 a5 = __ldg(W4 + 5);
        float  a6 = __ldg(W + 24);
        w[0][0]=a0.x; w[0][1]=a0.y; w[0][2]=a0.z; w[0][3]=a0.w; w[0][4]=a1.x;
        w[1][0]=a1.y; w[1][1]=a1.z; w[1][2]=a1.w; w[1][3]=a2.x; w[1][4]=a2.y;
        w[2][0]=a2.z; w[2][1]=a2.w; w[2][2]=a3.x; w[2][3]=a3.y; w[2][4]=a3.z;
        w[3][0]=a3.w; w[3][1]=a4.x; w[3][2]=a4.y; w[3][3]=a4.z; w[3][4]=a4.w;
        w[4][0]=a5.x; w[4][1]=a5.y; w[4][2]=a5.z; w[4][3]=a5.w; w[4][4]=a6;
        const float4* b4 = reinterpret_cast<const float4*>(b);
        float4 bv = __ldg(b4);
        bb[0]=bv.x; bb[1]=bv.y; bb[2]=bv.z; bb[3]=bv.w; bb[4]=__ldg(b + 4);
    }

    // ---- wait only for THIS warp's chunk (acquire: LDS follows) ----
    asm volatile(
        "{\n\t"
        ".reg .pred P;\n\t"
        "WAIT_%=:\n\t"
        "mbarrier.try_wait.parity.acquire.cta.shared::cta.b64 P, [%0], 0, 0x989680;\n\t"
        "@P bra DONE_%=;\n\t"
        "bra WAIT_%=;\n\t"
        "DONE_%=:\n\t"
        "}"
        :: "r"(mb) : "memory");

    // ---- two 128-row passes; store first half while computing second ----
#pragma unroll
    for (int p = 0; p < 2; p++) {
        const int base4 = wid * WARP_F4 + p * HALF_F4 + 5 * lane;

        // own 4 rows via 5x LDS.128 (80 B stride, conflict-free)
        float4 v[5];
#pragma unroll
        for (int k = 0; k < 5; k++)
            v[k] = buf[base4 + k];

        float xr[4][5];
        xr[0][0]=v[0].x; xr[0][1]=v[0].y; xr[0][2]=v[0].z; xr[0][3]=v[0].w; xr[0][4]=v[1].x;
        xr[1][0]=v[1].y; xr[1][1]=v[1].z; xr[1][2]=v[1].w; xr[1][3]=v[2].x; xr[1][4]=v[2].y;
        xr[2][0]=v[2].z; xr[2][1]=v[2].w; xr[2][2]=v[3].x; xr[2][3]=v[3].y; xr[2][4]=v[3].z;
        xr[3][0]=v[3].w; xr[3][1]=v[4].x; xr[3][2]=v[4].y; xr[3][3]=v[4].z; xr[3][4]=v[4].w;

        float zr[4][5];
#pragma unroll
        for (int r = 0; r < 4; r++) {
#pragma unroll
            for (int j = 0; j < 5; j++) {
                float h = bb[j];
#pragma unroll
                for (int k = 0; k < 5; k++)
                    h = fmaf(xr[r][k], w[j][k], h);
                zr[r][j] = fmaxf(-h, NEG_CLAMP);
            }
        }

        // in-place write-back to own slots (within-thread hazard only)
        buf[base4 + 0] = make_float4(zr[0][0], zr[0][1], zr[0][2], zr[0][3]);
        buf[base4 + 1] = make_float4(zr[0][4], zr[1][0], zr[1][1], zr[1][2]);
        buf[base4 + 2] = make_float4(zr[1][3], zr[1][4], zr[2][0], zr[2][1]);
        buf[base4 + 3] = make_float4(zr[2][2], zr[2][3], zr[2][4], zr[3][0]);
        buf[base4 + 4] = make_float4(zr[3][1], zr[3][2], zr[3][3], zr[3][4]);

        // per-warp bulk store of this half (2560 B); overlaps next pass
        __syncwarp();
        if (lane == 0) {
            asm volatile("fence.proxy.async.shared::cta;" ::: "memory");
            asm volatile("cp.async.bulk.global.shared::cta.bulk_group"
                         ".L2::cache_hint [%0], [%1], %2, %3;"
                         :: "l"((unsigned long long)(uintptr_t)
                                (out + base_f + p * HALF_FLOATS)),
                            "r"(sb + (unsigned)p * HALF_BYTES),
                            "r"(HALF_BYTES), "l"(pol_st) : "memory");
            asm volatile("cp.async.bulk.commit_group;" ::: "memory");
        }
    }

    // CTA must not exit while its stores still read smem.
    if (lane == 0)
        asm volatile("cp.async.bulk.wait_group.read 0;" ::: "memory");
}

extern "C" void kernel_launch(void* const* d_in, const int* in_sizes, int n_in,
                              void* d_out, int out_size)
{
    const float* x = (const float*)d_in[0];   // [B,5]
    const float* W = (const float*)d_in[1];   // [5,5]
    const float* b = (const float*)d_in[2];   // [5]
    float* out = (float*)d_out;               // [B,5]

    const long long B = in_sizes[0] / 5;      // 4194304
    const int threads = 128;
    const int blocks = (int)(B / 1024);       // 4096, exact cover

    qp_kernel<<<blocks, threads>>>(x, W, b, out);
}

// round 17
// speedup vs baseline: 1.0088x; 1.0088x over previous
#include <cuda_runtime.h>
#include <cuda_bf16.h>
#include <cstdint>

// qpNet: z = max(-(x @ W^T + b), -1/EPS), EPS=1e-3  =>  z = max(-h, -1000)
// x: [B,5] f32, W: [5,5] f32, b: [5] f32, out: [B,5] f32. B = 4194304.
//
// R17: warp-independent pipelines, DEPTH-2 loads per warp.
// Each warp owns 5120 B (256 rows) split into two 2560 B chunks with
// independent mbarriers: compute on chunk A while chunk B's load is in
// flight; A's store overlaps B's compute. 4096 CTAs x 128 thr; no
// block-wide sync anywhere.

#define NEG_CLAMP     (-1000.0f)   // -1/EPS
#define CTA_FLOATS    5120         // 1024 rows per CTA
#define WARP_FLOATS   1280         // 256 rows per warp
#define WARP_F4       320
#define HALF_FLOATS   640          // 128 rows per chunk
#define HALF_F4       160
#define WARP_BYTES    5120u
#define HALF_BYTES    2560u

__global__ __launch_bounds__(128) void qp_kernel(
    const float* __restrict__ x,
    const float* __restrict__ W,
    const float* __restrict__ b,
    float* __restrict__ out)
{
    __shared__ alignas(128) float4 buf[1280];           // 20 KB, in-place
    __shared__ alignas(8)   unsigned long long mbar[8]; // 2 per warp

    const int tid  = threadIdx.x;
    const int wid  = tid >> 5;
    const int lane = tid & 31;

    const unsigned mb0 = (unsigned)__cvta_generic_to_shared(&mbar[2 * wid]);
    const unsigned sb  = (unsigned)__cvta_generic_to_shared(buf)
                         + (unsigned)wid * WARP_BYTES;

    const long long base_f = (long long)blockIdx.x * CTA_FLOATS
                           + (long long)wid * WARP_FLOATS;

    uint64_t pol_ld;
    asm("createpolicy.fractional.L2::evict_last.b64 %0, 1.0;" : "=l"(pol_ld));

    // ---- warp-private: init 2 mbarriers, issue BOTH 2560 B loads ----
    if (lane == 0) {
        asm volatile("mbarrier.init.shared.b64 [%0], %1;" :: "r"(mb0),     "r"(1u));
        asm volatile("mbarrier.init.shared.b64 [%0], %1;" :: "r"(mb0 + 8), "r"(1u));
    }
    __syncwarp();
    if (lane == 0) {
#pragma unroll
        for (int p = 0; p < 2; p++) {
            asm volatile("mbarrier.arrive.expect_tx.shared.b64 _, [%0], %1;"
                         :: "r"(mb0 + 8u * p), "r"(HALF_BYTES) : "memory");
            asm volatile("cp.async.bulk.shared::cta.global.mbarrier::complete_tx::bytes"
                         ".L2::cache_hint [%0], [%1], %2, [%3], %4;"
                         :: "r"(sb + (unsigned)p * HALF_BYTES),
                            "l"((unsigned long long)(uintptr_t)
                                (x + base_f + p * HALF_FLOATS)),
                            "r"(HALF_BYTES), "r"(mb0 + 8u * p), "l"(pol_ld)
                         : "memory");
        }
    }

    // ---- W [5,5] + b [5] while both TMA loads are in flight ----
    float w[5][5], bb[5];
    {
        const float4* W4 = reinterpret_cast<const float4*>(W);
        float4 a0 = __ldg(W4 + 0);
        float4 a1 = __ldg(W4 + 1);
        float4 a2 = __ldg(W4 + 2);
        float4 a3 = __ldg(W4 + 3);
        float4 a4 = __ldg(W4 + 4);
        float4 a5 = __ldg(W4 + 5);
        float  a6 = __ldg(W + 24);
        w[0][0]=a0.x; w[0][1]=a0.y; w[0][2]=a0.z; w[0][3]=a0.w; w[0][4]=a1.x;
        w[1][0]=a1.y; w[1][1]=a1.z; w[1][2]=a1.w; w[1][3]=a2.x; w[1][4]=a2.y;
        w[2][0]=a2.z; w[2][1]=a2.w; w[2][2]=a3.x; w[2][3]=a3.y; w[2][4]=a3.z;
        w[3][0]=a3.w; w[3][1]=a4.x; w[3][2]=a4.y; w[3][3]=a4.z; w[3][4]=a4.w;
        w[4][0]=a5.x; w[4][1]=a5.y; w[4][2]=a5.z; w[4][3]=a5.w; w[4][4]=a6;
        const float4* b4 = reinterpret_cast<const float4*>(b);
        float4 bv = __ldg(b4);
        bb[0]=bv.x; bb[1]=bv.y; bb[2]=bv.z; bb[3]=bv.w; bb[4]=__ldg(b + 4);
    }

    // ---- two passes: wait chunk p, compute, store; B's load overlaps A ----
#pragma unroll
    for (int p = 0; p < 2; p++) {
        // wait only for THIS chunk (acquire: LDS follows)
        asm volatile(
            "{\n\t"
            ".reg .pred P;\n\t"
            "WAIT_%=:\n\t"
            "mbarrier.try_wait.parity.acquire.cta.shared::cta.b64 P, [%0], 0, 0x989680;\n\t"
            "@P bra DONE_%=;\n\t"
            "bra WAIT_%=;\n\t"
            "DONE_%=:\n\t"
            "}"
            :: "r"(mb0 + 8u * p) : "memory");

        const int base4 = wid * WARP_F4 + p * HALF_F4 + 5 * lane;

        // own 4 rows via 5x LDS.128 (80 B stride, conflict-free)
        float4 v[5];
#pragma unroll
        for (int k = 0; k < 5; k++)
            v[k] = buf[base4 + k];

        float xr[4][5];
        xr[0][0]=v[0].x; xr[0][1]=v[0].y; xr[0][2]=v[0].z; xr[0][3]=v[0].w; xr[0][4]=v[1].x;
        xr[1][0]=v[1].y; xr[1][1]=v[1].z; xr[1][2]=v[1].w; xr[1][3]=v[2].x; xr[1][4]=v[2].y;
        xr[2][0]=v[2].z; xr[2][1]=v[2].w; xr[2][2]=v[3].x; xr[2][3]=v[3].y; xr[2][4]=v[3].z;
        xr[3][0]=v[3].w; xr[3][1]=v[4].x; xr[3][2]=v[4].y; xr[3][3]=v[4].z; xr[3][4]=v[4].w;

        float zr[4][5];
#pragma unroll
        for (int r = 0; r < 4; r++) {
#pragma unroll
            for (int j = 0; j < 5; j++) {
                float h = bb[j];
#pragma unroll
                for (int k = 0; k < 5; k++)
                    h = fmaf(xr[r][k], w[j][k], h);
                zr[r][j] = fmaxf(-h, NEG_CLAMP);
            }
        }

        // in-place write-back to own slots (within-thread hazard only)
        buf[base4 + 0] = make_float4(zr[0][0], zr[0][1], zr[0][2], zr[0][3]);
        buf[base4 + 1] = make_float4(zr[0][4], zr[1][0], zr[1][1], zr[1][2]);
        buf[base4 + 2] = make_float4(zr[1][3], zr[1][4], zr[2][0], zr[2][1]);
        buf[base4 + 3] = make_float4(zr[2][2], zr[2][3], zr[2][4], zr[3][0]);
        buf[base4 + 4] = make_float4(zr[3][1], zr[3][2], zr[3][3], zr[3][4]);

        // per-warp bulk store of this chunk (overlaps next pass compute)
        __syncwarp();
        if (lane == 0) {
            asm volatile("fence.proxy.async.shared::cta;" ::: "memory");
            asm volatile("cp.async.bulk.global.shared::cta.bulk_group [%0], [%1], %2;"
                         :: "l"((unsigned long long)(uintptr_t)
                                (out + base_f + p * HALF_FLOATS)),
                            "r"(sb + (unsigned)p * HALF_BYTES),
                            "r"(HALF_BYTES) : "memory");
            asm volatile("cp.async.bulk.commit_group;" ::: "memory");
        }
    }

    // CTA must not exit while its stores still read smem.
    if (lane == 0)
        asm volatile("cp.async.bulk.wait_group.read 0;" ::: "memory");
}

extern "C" void kernel_launch(void* const* d_in, const int* in_sizes, int n_in,
                              void* d_out, int out_size)
{
    const float* x = (const float*)d_in[0];   // [B,5]
    const float* W = (const float*)d_in[1];   // [5,5]
    const float* b = (const float*)d_in[2];   // [5]
    float* out = (float*)d_out;               // [B,5]

    const long long B = in_sizes[0] / 5;      // 4194304
    const int threads = 128;
    const int blocks = (int)(B / 1024);       // 4096, exact cover

    qp_kernel<<<blocks, threads>>>(x, W, b, out);
}